// round 11
// baseline (speedup 1.0000x reference)
#include <cuda_runtime.h>
#include <cuda_bf16.h>
#include <math.h>
#include <stdint.h>

// Problem constants
#define NB   8192          // batch
#define NV   778           // vertices
#define KC   512           // padded K stride (3x160 split: [Xhi|Xlo|Xhi] vs [Chi|Chi|Clo])
#define NP   1024          // padded N = 16 joints * 64 (63 used per joint)
#define BKC  32            // k per pipeline chunk
#define NCH  15            // 480 / 32 used chunks
#define NVS  8             // vertex splits for precomp_C
#define VPB  104           // verts per split block (zero-padded; 8*104=832>=778)
#define VST  108           // smem v-stride (floats): 27x16B, conflict-free for k<21

// ---------------- scratch (device globals; zero-initialized at load) ----------------
__device__ __nv_bfloat16 g_Xh[(size_t)NB * KC];   // [b][k]  A operand bf16
__device__ __nv_bfloat16 g_Cb[(size_t)KC * NP];   // [k][j*64 + k21*3 + d]  B operand bf16
__device__ float  g_Cp[NVS * 146 * 1008];         // fp32 partials of C
__device__ float  g_A[NB * 192];                  // [b][j][3x4]
__device__ float  g_P[(size_t)9 * NB * 64];       // joint partials: 8 j-pairs + W-term
__device__ float  g_Js[480];
__device__ float  g_J0[48];
__device__ float  g_W[336];

// ---------------- helpers ----------------
__device__ __forceinline__ __nv_bfloat16 hb(float x) { return __float2bfloat16(x); }
__device__ __forceinline__ __nv_bfloat16 lb(float x) {
    return __float2bfloat16(x - __bfloat162float(__float2bfloat16(x)));
}
__device__ __forceinline__ void ldsm_x4(uint32_t* r, uint32_t addr) {
    asm volatile("ldmatrix.sync.aligned.m8n8.x4.shared.b16 {%0,%1,%2,%3}, [%4];"
                 : "=r"(r[0]), "=r"(r[1]), "=r"(r[2]), "=r"(r[3]) : "r"(addr));
}
__device__ __forceinline__ void ldsm_x2_t(uint32_t* r, uint32_t addr) {
    asm volatile("ldmatrix.sync.aligned.m8n8.x2.trans.shared.b16 {%0,%1}, [%2];"
                 : "=r"(r[0]), "=r"(r[1]) : "r"(addr));
}
__device__ __forceinline__ void mma16816(float* d, const uint32_t* a, const uint32_t* b) {
    asm volatile("mma.sync.aligned.m16n8k16.row.col.f32.bf16.bf16.f32 "
                 "{%0,%1,%2,%3}, {%4,%5,%6,%7}, {%8,%9}, {%0,%1,%2,%3};"
                 : "+f"(d[0]), "+f"(d[1]), "+f"(d[2]), "+f"(d[3])
                 : "r"(a[0]), "r"(a[1]), "r"(a[2]), "r"(a[3]), "r"(b[0]), "r"(b[1]));
}
__device__ __forceinline__ void cp16(uint32_t saddr, const void* g) {
    asm volatile("cp.async.cg.shared.global [%0], [%1], 16;" :: "r"(saddr), "l"(g) : "memory");
}
#define CP_COMMIT() asm volatile("cp.async.commit_group;" ::: "memory")
#define CP_WAIT1()  asm volatile("cp.async.wait_group 1;" ::: "memory")
#define CP_WAIT0()  asm volatile("cp.async.wait_group 0;" ::: "memory")
// A staging: 64B rows (32 halfs), swizzle bits[5:4] ^= bits[7:6]
#define SWA(o) ((o) ^ (((o) >> 2) & 0x30))
// B staging: 256B rows (128 halfs), swizzle bits[6:4] ^= bits[10:8]
#define SWB(o) ((o) ^ (((o) >> 4) & 0x70))

// =====================================================================
// Kernel 1: precomp_part — blocks 0..1167: C partials, v-transposed smem,
//           float4 inner loop; blocks 1168..1239: small reductions.
// =====================================================================
__global__ __launch_bounds__(384) void precomp_part(
    const float* __restrict__ vt, const float* __restrict__ sd,
    const float* __restrict__ pd, const float* __restrict__ Jr,
    const float* __restrict__ wts)
{
    __shared__ float sWt[16][VST];
    __shared__ float sJt[21][VST];
    __shared__ float sBt[3][VST];

    int t = threadIdx.x;
    int bid = blockIdx.x;

    if (bid < 146 * NVS) {
        int f  = bid >> 3;
        int vs = bid & 7;
        const float* brow = (f == 0) ? vt : ((f <= 10) ? (sd + (f - 1) * 2334)
                                                       : (pd + (f - 11) * 2334));
        int vstart = vs * VPB;

        // stage transposed (zero-padded beyond NV)
        for (int i = t; i < 16 * VPB; i += 384) {
            int vv = i >> 4, j = i & 15;
            int v = vstart + vv;
            sWt[j][vv] = (v < NV) ? wts[v * 16 + j] : 0.f;
        }
        for (int i = t; i < 21 * VPB; i += 384) {
            int vv = i / 21, k = i - vv * 21;
            int v = vstart + vv;
            sJt[k][vv] = (v < NV) ? Jr[v * 21 + k] : 0.f;
        }
        for (int i = t; i < 3 * VPB; i += 384) {
            int vv = i / 3, d = i - vv * 3;
            int v = vstart + vv;
            sBt[d][vv] = (v < NV) ? brow[v * 3 + d] : 0.f;
        }
        __syncthreads();

        if (t < 336) {
            int j = t / 21, k = t - j * 21;
            float a0 = 0.f, a1 = 0.f, a2 = 0.f;
            #pragma unroll
            for (int v4 = 0; v4 < VPB; v4 += 4) {
                float4 wv = *(const float4*)&sWt[j][v4];
                float4 jv = *(const float4*)&sJt[k][v4];
                float4 b0 = *(const float4*)&sBt[0][v4];
                float4 b1 = *(const float4*)&sBt[1][v4];
                float4 b2 = *(const float4*)&sBt[2][v4];
                float p;
                p = wv.x * jv.x; a0 = fmaf(p, b0.x, a0); a1 = fmaf(p, b1.x, a1); a2 = fmaf(p, b2.x, a2);
                p = wv.y * jv.y; a0 = fmaf(p, b0.y, a0); a1 = fmaf(p, b1.y, a1); a2 = fmaf(p, b2.y, a2);
                p = wv.z * jv.z; a0 = fmaf(p, b0.z, a0); a1 = fmaf(p, b1.z, a1); a2 = fmaf(p, b2.z, a2);
                p = wv.w * jv.w; a0 = fmaf(p, b0.w, a0); a1 = fmaf(p, b1.w, a1); a2 = fmaf(p, b2.w, a2);
            }
            float* dst = g_Cp + ((size_t)vs * 146 + f) * 1008 + t * 3;
            dst[0] = a0; dst[1] = a1; dst[2] = a2;
        }
    } else {
        int gw   = (bid - 146 * NVS) * 12 + (t >> 5);    // 0..863
        int lane = t & 31;
        float acc = 0.f;
        if (gw < 480) {                 // Js[s][j][c]
            int s = gw / 48, r = gw % 48, j = r / 3, c = r % 3;
            for (int v = lane; v < NV; v += 32)
                acc = fmaf(Jr[v * 21 + j], sd[s * 2334 + v * 3 + c], acc);
        } else if (gw < 528) {          // J0[j][c]
            int idx = gw - 480, j = idx / 3, c = idx % 3;
            for (int v = lane; v < NV; v += 32)
                acc = fmaf(Jr[v * 21 + j], vt[v * 3 + c], acc);
        } else {                        // W[k][j]
            int idx = gw - 528, k = idx / 16, j = idx % 16;
            for (int v = lane; v < NV; v += 32)
                acc = fmaf(Jr[v * 21 + k], wts[v * 16 + j], acc);
        }
        #pragma unroll
        for (int off = 16; off > 0; off >>= 1)
            acc += __shfl_down_sync(0xffffffffu, acc, off);
        if (lane == 0) {
            if (gw < 480)      g_Js[gw] = acc;
            else if (gw < 528) g_J0[gw - 480] = acc;
            else               g_W[gw - 528] = acc;
        }
    }
}

// =====================================================================
// Kernel 2: fk_kernel — blocks 0..1023: per-batch FK (g_Xh, g_A) AND the
//           W-translation term -> g_P slot 8;
//           blocks 1024..1215: combine C partials -> bf16, padded-j layout.
// =====================================================================
__global__ __launch_bounds__(256) void fk_kernel(
    const float* __restrict__ beta, const float* __restrict__ theta,
    const float* __restrict__ wrist, const float* __restrict__ hc,
    const float* __restrict__ hm)
{
    if (blockIdx.x >= 1024) {
        // ---- combine C partials, write to column j*64 + k21*3 + c ----
        int idx = (blockIdx.x - 1024) * 256 + threadIdx.x;   // (f, o336)
        if (idx >= 146 * 336) return;
        int f = idx / 336, o = idx % 336;
        int j = o / 21, k21 = o % 21;
        int col = j * 64 + k21 * 3;
        #pragma unroll
        for (int c = 0; c < 3; c++) {
            int o3 = o * 3 + c;
            float v = 0.f;
            #pragma unroll
            for (int vs = 0; vs < NVS; vs++)
                v += g_Cp[((size_t)vs * 146 + f) * 1008 + o3];
            g_Cb[(size_t)f * NP + col + c]         = hb(v);
            g_Cb[(size_t)(160 + f) * NP + col + c] = hb(v);
            g_Cb[(size_t)(320 + f) * NP + col + c] = lb(v);
        }
        return;
    }

    __shared__ float sE[8][48];
    __shared__ float sR[8][16][9];
    __shared__ float sJ[8][16][3];
    __shared__ float sG[8][16][12];
    __shared__ float sX[8][160];
    __shared__ float sA[8][192];

    int w = threadIdx.x >> 5, lane = threadIdx.x & 31;
    int b = blockIdx.x * 8 + w;

    // zero X row (incl. pads 146..159)
    for (int e = lane; e < 160; e += 32) sX[w][e] = 0.f;

    for (int e = lane; e < 45; e += 32) {
        float v = hm[e];
        #pragma unroll
        for (int s = 0; s < 10; s++)
            v = fmaf(theta[b * 10 + s], hc[s * 45 + e], v);
        sE[w][e] = v;
    }
    __syncwarp();

    if (lane < 16) {
        float r0, r1, r2;
        if (lane == 0) { r0 = wrist[b * 3]; r1 = wrist[b * 3 + 1]; r2 = wrist[b * 3 + 2]; }
        else { int e = (lane - 1) * 3; r0 = sE[w][e]; r1 = sE[w][e + 1]; r2 = sE[w][e + 2]; }
        float t0 = r0 + 1e-8f, t1 = r1 + 1e-8f, t2 = r2 + 1e-8f;
        float ang = sqrtf(t0 * t0 + t1 * t1 + t2 * t2);
        float inv = 1.0f / ang;
        float x = r0 * inv, y = r1 * inv, z = r2 * inv;
        float s, c;
        sincosf(ang, &s, &c);
        float ic = 1.0f - c;
        float R[9];
        R[0] = 1.0f - ic * (y * y + z * z);
        R[1] = -s * z + ic * x * y;
        R[2] =  s * y + ic * x * z;
        R[3] =  s * z + ic * x * y;
        R[4] = 1.0f - ic * (x * x + z * z);
        R[5] = -s * x + ic * y * z;
        R[6] = -s * y + ic * x * z;
        R[7] =  s * x + ic * y * z;
        R[8] = 1.0f - ic * (x * x + y * y);
        #pragma unroll
        for (int m = 0; m < 9; m++) sR[w][lane][m] = R[m];
        if (lane >= 1) {
            int s0 = 11 + (lane - 1) * 9;
            #pragma unroll
            for (int m = 0; m < 9; m++)
                sX[w][s0 + m] = R[m] - ((m == 0 || m == 4 || m == 8) ? 1.0f : 0.0f);
        }
    }
    if (lane == 0)  sX[w][0] = 1.0f;
    if (lane < 10)  sX[w][1 + lane] = beta[b * 10 + lane];

    if (lane < 16) {
        float jx = g_J0[lane * 3 + 0], jy = g_J0[lane * 3 + 1], jz = g_J0[lane * 3 + 2];
        #pragma unroll
        for (int s = 0; s < 10; s++) {
            float bs = beta[b * 10 + s];
            jx = fmaf(bs, g_Js[s * 48 + lane * 3 + 0], jx);
            jy = fmaf(bs, g_Js[s * 48 + lane * 3 + 1], jy);
            jz = fmaf(bs, g_Js[s * 48 + lane * 3 + 2], jz);
        }
        sJ[w][lane][0] = jx; sJ[w][lane][1] = jy; sJ[w][lane][2] = jz;
    }
    __syncwarp();

    if (lane == 0) {
        #pragma unroll
        for (int c = 0; c < 3; c++) {
            #pragma unroll
            for (int d = 0; d < 3; d++) sG[w][0][c * 4 + d] = sR[w][0][c * 3 + d];
            sG[w][0][c * 4 + 3] = sJ[w][0][c];
        }
    }
    __syncwarp();

    if (lane < 5) {
        float pr[9], pt[3];
        #pragma unroll
        for (int c = 0; c < 3; c++) {
            #pragma unroll
            for (int d = 0; d < 3; d++) pr[c * 3 + d] = sG[w][0][c * 4 + d];
            pt[c] = sG[w][0][c * 4 + 3];
        }
        int p = 0;
        #pragma unroll
        for (int st = 0; st < 3; st++) {
            int j = 1 + lane * 3 + st;
            float rj[9];
            #pragma unroll
            for (int m = 0; m < 9; m++) rj[m] = sR[w][j][m];
            float nr[9], nt[3];
            #pragma unroll
            for (int c = 0; c < 3; c++)
                #pragma unroll
                for (int d = 0; d < 3; d++)
                    nr[c * 3 + d] = pr[c * 3 + 0] * rj[0 * 3 + d]
                                  + pr[c * 3 + 1] * rj[1 * 3 + d]
                                  + pr[c * 3 + 2] * rj[2 * 3 + d];
            float dx = sJ[w][j][0] - sJ[w][p][0];
            float dy = sJ[w][j][1] - sJ[w][p][1];
            float dz = sJ[w][j][2] - sJ[w][p][2];
            #pragma unroll
            for (int c = 0; c < 3; c++)
                nt[c] = pr[c * 3 + 0] * dx + pr[c * 3 + 1] * dy + pr[c * 3 + 2] * dz + pt[c];
            #pragma unroll
            for (int c = 0; c < 3; c++) {
                #pragma unroll
                for (int d = 0; d < 3; d++) sG[w][j][c * 4 + d] = nr[c * 3 + d];
                sG[w][j][c * 4 + 3] = nt[c];
            }
            #pragma unroll
            for (int m = 0; m < 9; m++) pr[m] = nr[m];
            pt[0] = nt[0]; pt[1] = nt[1]; pt[2] = nt[2];
            p = j;
        }
    }
    __syncwarp();

    if (lane < 16) {
        float jx = sJ[w][lane][0], jy = sJ[w][lane][1], jz = sJ[w][lane][2];
        #pragma unroll
        for (int c = 0; c < 3; c++) {
            float a0 = sG[w][lane][c * 4 + 0];
            float a1 = sG[w][lane][c * 4 + 1];
            float a2 = sG[w][lane][c * 4 + 2];
            float at = sG[w][lane][c * 4 + 3] - (a0 * jx + a1 * jy + a2 * jz);
            int base = lane * 12 + c * 4;
            sA[w][base + 0] = a0; sA[w][base + 1] = a1;
            sA[w][base + 2] = a2; sA[w][base + 3] = at;
        }
    }
    __syncwarp();

    // ---- coalesced global stores ----
    // X row: 512 bf16 = 256 b32, pattern [hi(0..159) | lo(0..159) | hi(0..159) | 0 x32]
    {
        __nv_bfloat162* xr2 = (__nv_bfloat162*)(g_Xh + (size_t)b * KC);
        for (int i = lane; i < 256; i += 32) {
            int p0 = 2 * i, p1 = p0 + 1;
            __nv_bfloat16 v0, v1;
            v0 = (p0 < 160) ? hb(sX[w][p0])
               : (p0 < 320) ? lb(sX[w][p0 - 160])
               : (p0 < 480) ? hb(sX[w][p0 - 320]) : hb(0.f);
            v1 = (p1 < 160) ? hb(sX[w][p1])
               : (p1 < 320) ? lb(sX[w][p1 - 160])
               : (p1 < 480) ? hb(sX[w][p1 - 320]) : hb(0.f);
            xr2[i] = __nv_bfloat162(v0, v1);
        }
    }
    // A row: 48 float4
    {
        float4* ar = (float4*)(g_A + (size_t)b * 192);
        const float4* sa = (const float4*)&sA[w][0];
        for (int i = lane; i < 48; i += 32) ar[i] = sa[i];
    }
    // W-translation term -> g_P slot 8: sum_j A[b][j][c*4+3] * W[k][j]
    for (int o = lane; o < 63; o += 32) {
        int k = (o * 21846) >> 16;      // o/3 for o < 63
        int c = o - k * 3;
        float acc = 0.f;
        #pragma unroll
        for (int j = 0; j < 16; j++)
            acc = fmaf(sA[w][j * 12 + c * 4 + 3], g_W[k * 16 + j], acc);
        g_P[((size_t)8 * NB + b) * 64 + o] = acc;
    }
}

// =====================================================================
// Kernel 3: FUSED bf16 GEMM + joint contraction.
// GEMM tile 128x128 (bm=128 batches, bn=128 cols = 2 complete joints).
// Epilogue: stage fp32 tile in smem, contract with A[b, j0..j0+1], write
// partials to private slice g_P[jp][b][64] (plain coalesced stores).
// =====================================================================
__global__ __launch_bounds__(256) void mma_fused()
{
    __shared__ __align__(128) char smem[49152];

    const int tid = threadIdx.x;
    const int wid = tid >> 5, lane = tid & 31;
    const int bn0 = blockIdx.x * 128;
    const int bm0 = blockIdx.y * 128;
    const int j0  = blockIdx.x * 2;          // first joint of this N tile
    const int warp_m = (wid & 1) * 64;
    const int warp_n = (wid >> 1) * 32;

    const uint32_t smA_u = (uint32_t)__cvta_generic_to_shared(smem);
    const uint32_t smB_u = smA_u + 24576;

    float acc[4][4][4];
    #pragma unroll
    for (int mt = 0; mt < 4; mt++)
        #pragma unroll
        for (int nt = 0; nt < 4; nt++)
            #pragma unroll
            for (int q = 0; q < 4; q++) acc[mt][nt][q] = 0.f;

    auto load_chunk = [&](int kc, int st) {
        #pragma unroll
        for (int i = 0; i < 2; i++) {
            int idx = i * 256 + tid;
            int row = idx >> 2, c16 = idx & 3;
            uint32_t off = SWA((uint32_t)(row * 64 + c16 * 16));
            cp16(smA_u + st * 8192 + off,
                 g_Xh + (size_t)(bm0 + row) * KC + kc * BKC + c16 * 8);
        }
        #pragma unroll
        for (int i = 0; i < 2; i++) {
            int idx = i * 256 + tid;
            int row = idx >> 4, c16 = idx & 15;
            uint32_t off = SWB((uint32_t)(row * 256 + c16 * 16));
            cp16(smB_u + st * 8192 + off,
                 g_Cb + (size_t)(kc * BKC + row) * NP + bn0 + c16 * 8);
        }
    };

    load_chunk(0, 0); CP_COMMIT();
    load_chunk(1, 1); CP_COMMIT();

    const int r15 = lane & 15;
    const int kq  = lane >> 4;

    #pragma unroll 1
    for (int kc = 0; kc < NCH; kc++) {
        CP_WAIT1();
        __syncthreads();
        int nk = kc + 2;
        if (nk < NCH) load_chunk(nk, nk % 3);
        CP_COMMIT();

        int st = kc % 3;
        #pragma unroll
        for (int ks = 0; ks < 2; ks++) {
            uint32_t a[4][4], b[4][2];
            #pragma unroll
            for (int mt = 0; mt < 4; mt++) {
                uint32_t off = (uint32_t)((warp_m + mt * 16 + r15) * 64
                                          + (ks * 16 + kq * 8) * 2);
                ldsm_x4(a[mt], smA_u + st * 8192 + SWA(off));
            }
            #pragma unroll
            for (int nt = 0; nt < 4; nt++) {
                uint32_t off = (uint32_t)((ks * 16 + r15) * 256
                                          + (warp_n + nt * 8) * 2);
                ldsm_x2_t(b[nt], smB_u + st * 8192 + SWB(off));
            }
            #pragma unroll
            for (int mt = 0; mt < 4; mt++)
                #pragma unroll
                for (int nt = 0; nt < 4; nt++)
                    mma16816(acc[mt][nt], a[mt], b[nt]);
        }
    }

    // ================= fused epilogue =================
    CP_WAIT0();
    __syncthreads();      // pipeline buffers dead; smem arena is free

    float* sA2 = (float*)smem;                 // [128 batches][24] = 12 KB
    float* sM  = (float*)(smem + 12288);       // [64 rows][132]    = 33 KB

    // load A slice for this CTA's 128 batches, joints j0, j0+1 (6 float4/batch)
    {
        const float4* gA4 = (const float4*)(g_A + (size_t)bm0 * 192);
        float4* sA4 = (float4*)sA2;
        #pragma unroll
        for (int i = tid; i < 768; i += 256) {
            int bl = i / 6, q = i - bl * 6;
            sA4[bl * 6 + q] = gA4[bl * 48 + j0 * 3 + q];
        }
    }

    float* pout = g_P + (size_t)blockIdx.x * (NB * 64);

    #pragma unroll
    for (int h = 0; h < 2; h++) {
        // warps owning rows [h*64, h*64+64) store their accumulators
        if ((wid & 1) == h) {
            #pragma unroll
            for (int mt = 0; mt < 4; mt++) {
                int rl = mt * 16 + (lane >> 2);
                #pragma unroll
                for (int nt = 0; nt < 4; nt++) {
                    int c = warp_n + nt * 8 + (lane & 3) * 2;
                    *(float2*)&sM[rl * 132 + c] =
                        make_float2(acc[mt][nt][0], acc[mt][nt][1]);
                    *(float2*)&sM[(rl + 8) * 132 + c] =
                        make_float2(acc[mt][nt][2], acc[mt][nt][3]);
                }
            }
        }
        __syncthreads();

        // contract: for each (batch-in-half, o<63): sum over 2 joints
        #pragma unroll
        for (int it = 0; it < 16; it++) {
            int idx = it * 256 + tid;            // 0..4095
            int bl = idx >> 6, o = idx & 63;
            if (o < 63) {
                int k = (o * 21846) >> 16;       // o/3
                int c = o - k * 3;
                int bglob = h * 64 + bl;
                const float* m = &sM[bl * 132 + k * 3];
                float4 a0 = *(const float4*)&sA2[bglob * 24 + c * 4];
                float4 a1 = *(const float4*)&sA2[bglob * 24 + 12 + c * 4];
                float acc2;
                acc2 = a0.x * m[0];
                acc2 = fmaf(a0.y, m[1], acc2);
                acc2 = fmaf(a0.z, m[2], acc2);
                acc2 = fmaf(a1.x, m[64], acc2);
                acc2 = fmaf(a1.y, m[65], acc2);
                acc2 = fmaf(a1.z, m[66], acc2);
                pout[(size_t)(bm0 + bglob) * 64 + o] = acc2;
            }
        }
        __syncthreads();
    }
}

// =====================================================================
// Kernel 4: gather — out[b][o] = sum over 9 partial slices (8 j-pairs + W).
// =====================================================================
__global__ __launch_bounds__(256) void gather_kernel(float* __restrict__ out)
{
    int idx = blockIdx.x * 256 + threadIdx.x;    // 0 .. NB*64
    int o = idx & 63;
    int b = idx >> 6;
    if (o < 63) {
        float s = 0.f;
        #pragma unroll
        for (int p = 0; p < 9; p++)
            s += g_P[((size_t)p * NB << 6) + idx];
        out[(size_t)b * 63 + o] = s;
    }
}

// =====================================================================
extern "C" void kernel_launch(void* const* d_in, const int* in_sizes, int n_in,
                              void* d_out, int out_size)
{
    const float* beta  = (const float*)d_in[0];
    const float* theta = (const float*)d_in[1];
    const float* wrist = (const float*)d_in[2];
    const float* vt    = (const float*)d_in[3];
    const float* sd    = (const float*)d_in[4];
    const float* pd    = (const float*)d_in[5];
    const float* Jr    = (const float*)d_in[6];
    const float* hc    = (const float*)d_in[7];
    const float* hm    = (const float*)d_in[8];
    const float* wts   = (const float*)d_in[9];
    float* out = (float*)d_out;

    precomp_part<<<146 * NVS + 72, 384>>>(vt, sd, pd, Jr, wts);
    fk_kernel<<<1216, 256>>>(beta, theta, wrist, hc, hm);
    mma_fused<<<dim3(NP / 128, NB / 128), 256>>>();
    gather_kernel<<<NB * 64 / 256, 256>>>(out);
}

// round 12
// speedup vs baseline: 1.1826x; 1.1826x over previous
#include <cuda_runtime.h>
#include <cuda_bf16.h>
#include <math.h>
#include <stdint.h>

// Problem constants
#define NB   8192          // batch
#define NV   778           // vertices
#define KC   512           // padded K stride (3x160 split: [Xhi|Xlo|Xhi] vs [Chi|Chi|Clo])
#define NP   1024          // padded N = 16 joints * 64 (63 used per joint)
#define BKC  32            // k per pipeline chunk
#define NCH  15            // 480 / 32 used chunks
#define NVS  8             // vertex splits for precomp_C
#define VPB  98            // verts per split block (8*98=784>=778)
#define NFT  37            // f tiles of 4 (37*4=148>=146)

// ---------------- scratch (device globals; zero-initialized at load) ----------------
__device__ __nv_bfloat16 g_Xh[(size_t)NB * KC];   // [b][k]  A operand bf16
__device__ __nv_bfloat16 g_Cb[(size_t)KC * NP];   // [k][j*64 + k21*3 + d]  B operand bf16
__device__ float  g_Cp[NVS * 146 * 1008];         // fp32 partials of C
__device__ float  g_A[NB * 192];                  // [b][j][3x4]
__device__ float  g_Js[480];
__device__ float  g_J0[48];
__device__ float  g_W[336];

// ---------------- helpers ----------------
__device__ __forceinline__ __nv_bfloat16 hb(float x) { return __float2bfloat16(x); }
__device__ __forceinline__ __nv_bfloat16 lb(float x) {
    return __float2bfloat16(x - __bfloat162float(__float2bfloat16(x)));
}
__device__ __forceinline__ void ldsm_x4(uint32_t* r, uint32_t addr) {
    asm volatile("ldmatrix.sync.aligned.m8n8.x4.shared.b16 {%0,%1,%2,%3}, [%4];"
                 : "=r"(r[0]), "=r"(r[1]), "=r"(r[2]), "=r"(r[3]) : "r"(addr));
}
__device__ __forceinline__ void ldsm_x2_t(uint32_t* r, uint32_t addr) {
    asm volatile("ldmatrix.sync.aligned.m8n8.x2.trans.shared.b16 {%0,%1}, [%2];"
                 : "=r"(r[0]), "=r"(r[1]) : "r"(addr));
}
__device__ __forceinline__ void mma16816(float* d, const uint32_t* a, const uint32_t* b) {
    asm volatile("mma.sync.aligned.m16n8k16.row.col.f32.bf16.bf16.f32 "
                 "{%0,%1,%2,%3}, {%4,%5,%6,%7}, {%8,%9}, {%0,%1,%2,%3};"
                 : "+f"(d[0]), "+f"(d[1]), "+f"(d[2]), "+f"(d[3])
                 : "r"(a[0]), "r"(a[1]), "r"(a[2]), "r"(a[3]), "r"(b[0]), "r"(b[1]));
}
__device__ __forceinline__ void cp16(uint32_t saddr, const void* g) {
    asm volatile("cp.async.cg.shared.global [%0], [%1], 16;" :: "r"(saddr), "l"(g) : "memory");
}
#define CP_COMMIT() asm volatile("cp.async.commit_group;" ::: "memory")
#define CP_WAIT1()  asm volatile("cp.async.wait_group 1;" ::: "memory")
#define CP_WAIT0()  asm volatile("cp.async.wait_group 0;" ::: "memory")
// A staging: 64B rows (32 halfs), swizzle bits[5:4] ^= bits[7:6]
#define SWA(o) ((o) ^ (((o) >> 2) & 0x30))
// B staging: 256B rows (128 halfs), swizzle bits[6:4] ^= bits[10:8]
#define SWB(o) ((o) ^ (((o) >> 4) & 0x70))

// =====================================================================
// Kernel 1: precomp_part — blocks 0..295: C partials, f-blocked (4 f/block),
//           one o=(j,k) per thread, 12 FMA per 3x LDS.128-broadcast vertex;
//           blocks 296..367: small reductions (Js, J0, W).
// =====================================================================
__global__ __launch_bounds__(384) void precomp_part(
    const float* __restrict__ vt, const float* __restrict__ sd,
    const float* __restrict__ pd, const float* __restrict__ Jr,
    const float* __restrict__ wts)
{
    __shared__ float sW[VPB * 16];          // [v][j]
    __shared__ float sJr[VPB * 21];         // [v][k]
    __shared__ __align__(16) float sB[VPB * 12];   // [v][f'*3+d]

    int t = threadIdx.x;
    int bid = blockIdx.x;

    if (bid < NFT * NVS) {
        int ft = bid >> 3;
        int vs = bid & 7;
        int f0 = ft * 4;
        int vstart = vs * VPB;

        // stage w, Jr (zero-padded beyond NV)
        for (int i = t; i < VPB * 16; i += 384) {
            int vv = i >> 4, j = i & 15;
            int v = vstart + vv;
            sW[i] = (v < NV) ? wts[v * 16 + j] : 0.f;
        }
        for (int i = t; i < VPB * 21; i += 384) {
            int vv = i / 21, k = i - vv * 21;
            int v = vstart + vv;
            sJr[i] = (v < NV) ? Jr[v * 21 + k] : 0.f;
        }
        // stage 4 basis rows interleaved: sB[v][fp*3+d]
        #pragma unroll
        for (int fp = 0; fp < 4; fp++) {
            int f = f0 + fp;
            const float* brow = (f == 0) ? vt : ((f <= 10) ? (sd + (f - 1) * 2334)
                                                           : (pd + (f - 11) * 2334));
            bool fvalid = (f < 146);
            for (int i = t; i < VPB * 3; i += 384) {
                int vv = i / 3, d = i - vv * 3;
                int v = vstart + vv;
                sB[vv * 12 + fp * 3 + d] =
                    (fvalid && v < NV) ? brow[v * 3 + d] : 0.f;
            }
        }
        __syncthreads();

        if (t < 336) {
            int j = t / 21, k = t - j * 21;
            float acc[12];
            #pragma unroll
            for (int i = 0; i < 12; i++) acc[i] = 0.f;

            #pragma unroll 2
            for (int vv = 0; vv < VPB; vv++) {
                float p = sW[vv * 16 + j] * sJr[vv * 21 + k];
                float4 b0 = *(const float4*)&sB[vv * 12 + 0];
                float4 b1 = *(const float4*)&sB[vv * 12 + 4];
                float4 b2 = *(const float4*)&sB[vv * 12 + 8];
                acc[0]  = fmaf(p, b0.x, acc[0]);
                acc[1]  = fmaf(p, b0.y, acc[1]);
                acc[2]  = fmaf(p, b0.z, acc[2]);
                acc[3]  = fmaf(p, b0.w, acc[3]);
                acc[4]  = fmaf(p, b1.x, acc[4]);
                acc[5]  = fmaf(p, b1.y, acc[5]);
                acc[6]  = fmaf(p, b1.z, acc[6]);
                acc[7]  = fmaf(p, b1.w, acc[7]);
                acc[8]  = fmaf(p, b2.x, acc[8]);
                acc[9]  = fmaf(p, b2.y, acc[9]);
                acc[10] = fmaf(p, b2.z, acc[10]);
                acc[11] = fmaf(p, b2.w, acc[11]);
            }
            #pragma unroll
            for (int fp = 0; fp < 4; fp++) {
                int f = f0 + fp;
                if (f < 146) {
                    float* dst = g_Cp + ((size_t)vs * 146 + f) * 1008 + t * 3;
                    dst[0] = acc[fp * 3 + 0];
                    dst[1] = acc[fp * 3 + 1];
                    dst[2] = acc[fp * 3 + 2];
                }
            }
        }
    } else {
        int gw   = (bid - NFT * NVS) * 12 + (t >> 5);    // 0..863
        int lane = t & 31;
        float acc = 0.f;
        if (gw < 480) {                 // Js[s][j][c]
            int s = gw / 48, r = gw % 48, j = r / 3, c = r % 3;
            for (int v = lane; v < NV; v += 32)
                acc = fmaf(Jr[v * 21 + j], sd[s * 2334 + v * 3 + c], acc);
        } else if (gw < 528) {          // J0[j][c]
            int idx = gw - 480, j = idx / 3, c = idx % 3;
            for (int v = lane; v < NV; v += 32)
                acc = fmaf(Jr[v * 21 + j], vt[v * 3 + c], acc);
        } else {                        // W[k][j]
            int idx = gw - 528, k = idx / 16, j = idx % 16;
            for (int v = lane; v < NV; v += 32)
                acc = fmaf(Jr[v * 21 + k], wts[v * 16 + j], acc);
        }
        #pragma unroll
        for (int off = 16; off > 0; off >>= 1)
            acc += __shfl_down_sync(0xffffffffu, acc, off);
        if (lane == 0) {
            if (gw < 480)      g_Js[gw] = acc;
            else if (gw < 528) g_J0[gw - 480] = acc;
            else               g_W[gw - 528] = acc;
        }
    }
}

// =====================================================================
// Kernel 2: fk_kernel — blocks 0..1023: per-batch FK (g_Xh, g_A) AND the
//           W-translation term written to out[b][*] (initializes out);
//           blocks 1024..1215: combine C partials -> bf16, padded-j layout.
// =====================================================================
__global__ __launch_bounds__(256) void fk_kernel(
    const float* __restrict__ beta, const float* __restrict__ theta,
    const float* __restrict__ wrist, const float* __restrict__ hc,
    const float* __restrict__ hm, float* __restrict__ out)
{
    if (blockIdx.x >= 1024) {
        // ---- combine C partials, write to column j*64 + k21*3 + c ----
        int idx = (blockIdx.x - 1024) * 256 + threadIdx.x;   // (f, o336)
        if (idx >= 146 * 336) return;
        int f = idx / 336, o = idx % 336;
        int j = o / 21, k21 = o % 21;
        int col = j * 64 + k21 * 3;
        #pragma unroll
        for (int c = 0; c < 3; c++) {
            int o3 = o * 3 + c;
            float v = 0.f;
            #pragma unroll
            for (int vs = 0; vs < NVS; vs++)
                v += g_Cp[((size_t)vs * 146 + f) * 1008 + o3];
            g_Cb[(size_t)f * NP + col + c]         = hb(v);
            g_Cb[(size_t)(160 + f) * NP + col + c] = hb(v);
            g_Cb[(size_t)(320 + f) * NP + col + c] = lb(v);
        }
        return;
    }

    __shared__ float sE[8][48];
    __shared__ float sR[8][16][9];
    __shared__ float sJ[8][16][3];
    __shared__ float sG[8][16][12];
    __shared__ float sX[8][160];
    __shared__ float sA[8][192];

    int w = threadIdx.x >> 5, lane = threadIdx.x & 31;
    int b = blockIdx.x * 8 + w;

    // zero X row (incl. pads 146..159)
    for (int e = lane; e < 160; e += 32) sX[w][e] = 0.f;

    for (int e = lane; e < 45; e += 32) {
        float v = hm[e];
        #pragma unroll
        for (int s = 0; s < 10; s++)
            v = fmaf(theta[b * 10 + s], hc[s * 45 + e], v);
        sE[w][e] = v;
    }
    __syncwarp();

    if (lane < 16) {
        float r0, r1, r2;
        if (lane == 0) { r0 = wrist[b * 3]; r1 = wrist[b * 3 + 1]; r2 = wrist[b * 3 + 2]; }
        else { int e = (lane - 1) * 3; r0 = sE[w][e]; r1 = sE[w][e + 1]; r2 = sE[w][e + 2]; }
        float t0 = r0 + 1e-8f, t1 = r1 + 1e-8f, t2 = r2 + 1e-8f;
        float ang = sqrtf(t0 * t0 + t1 * t1 + t2 * t2);
        float inv = 1.0f / ang;
        float x = r0 * inv, y = r1 * inv, z = r2 * inv;
        float s, c;
        sincosf(ang, &s, &c);
        float ic = 1.0f - c;
        float R[9];
        R[0] = 1.0f - ic * (y * y + z * z);
        R[1] = -s * z + ic * x * y;
        R[2] =  s * y + ic * x * z;
        R[3] =  s * z + ic * x * y;
        R[4] = 1.0f - ic * (x * x + z * z);
        R[5] = -s * x + ic * y * z;
        R[6] = -s * y + ic * x * z;
        R[7] =  s * x + ic * y * z;
        R[8] = 1.0f - ic * (x * x + y * y);
        #pragma unroll
        for (int m = 0; m < 9; m++) sR[w][lane][m] = R[m];
        if (lane >= 1) {
            int s0 = 11 + (lane - 1) * 9;
            #pragma unroll
            for (int m = 0; m < 9; m++)
                sX[w][s0 + m] = R[m] - ((m == 0 || m == 4 || m == 8) ? 1.0f : 0.0f);
        }
    }
    if (lane == 0)  sX[w][0] = 1.0f;
    if (lane < 10)  sX[w][1 + lane] = beta[b * 10 + lane];

    if (lane < 16) {
        float jx = g_J0[lane * 3 + 0], jy = g_J0[lane * 3 + 1], jz = g_J0[lane * 3 + 2];
        #pragma unroll
        for (int s = 0; s < 10; s++) {
            float bs = beta[b * 10 + s];
            jx = fmaf(bs, g_Js[s * 48 + lane * 3 + 0], jx);
            jy = fmaf(bs, g_Js[s * 48 + lane * 3 + 1], jy);
            jz = fmaf(bs, g_Js[s * 48 + lane * 3 + 2], jz);
        }
        sJ[w][lane][0] = jx; sJ[w][lane][1] = jy; sJ[w][lane][2] = jz;
    }
    __syncwarp();

    if (lane == 0) {
        #pragma unroll
        for (int c = 0; c < 3; c++) {
            #pragma unroll
            for (int d = 0; d < 3; d++) sG[w][0][c * 4 + d] = sR[w][0][c * 3 + d];
            sG[w][0][c * 4 + 3] = sJ[w][0][c];
        }
    }
    __syncwarp();

    if (lane < 5) {
        float pr[9], pt[3];
        #pragma unroll
        for (int c = 0; c < 3; c++) {
            #pragma unroll
            for (int d = 0; d < 3; d++) pr[c * 3 + d] = sG[w][0][c * 4 + d];
            pt[c] = sG[w][0][c * 4 + 3];
        }
        int p = 0;
        #pragma unroll
        for (int st = 0; st < 3; st++) {
            int j = 1 + lane * 3 + st;
            float rj[9];
            #pragma unroll
            for (int m = 0; m < 9; m++) rj[m] = sR[w][j][m];
            float nr[9], nt[3];
            #pragma unroll
            for (int c = 0; c < 3; c++)
                #pragma unroll
                for (int d = 0; d < 3; d++)
                    nr[c * 3 + d] = pr[c * 3 + 0] * rj[0 * 3 + d]
                                  + pr[c * 3 + 1] * rj[1 * 3 + d]
                                  + pr[c * 3 + 2] * rj[2 * 3 + d];
            float dx = sJ[w][j][0] - sJ[w][p][0];
            float dy = sJ[w][j][1] - sJ[w][p][1];
            float dz = sJ[w][j][2] - sJ[w][p][2];
            #pragma unroll
            for (int c = 0; c < 3; c++)
                nt[c] = pr[c * 3 + 0] * dx + pr[c * 3 + 1] * dy + pr[c * 3 + 2] * dz + pt[c];
            #pragma unroll
            for (int c = 0; c < 3; c++) {
                #pragma unroll
                for (int d = 0; d < 3; d++) sG[w][j][c * 4 + d] = nr[c * 3 + d];
                sG[w][j][c * 4 + 3] = nt[c];
            }
            #pragma unroll
            for (int m = 0; m < 9; m++) pr[m] = nr[m];
            pt[0] = nt[0]; pt[1] = nt[1]; pt[2] = nt[2];
            p = j;
        }
    }
    __syncwarp();

    if (lane < 16) {
        float jx = sJ[w][lane][0], jy = sJ[w][lane][1], jz = sJ[w][lane][2];
        #pragma unroll
        for (int c = 0; c < 3; c++) {
            float a0 = sG[w][lane][c * 4 + 0];
            float a1 = sG[w][lane][c * 4 + 1];
            float a2 = sG[w][lane][c * 4 + 2];
            float at = sG[w][lane][c * 4 + 3] - (a0 * jx + a1 * jy + a2 * jz);
            int base = lane * 12 + c * 4;
            sA[w][base + 0] = a0; sA[w][base + 1] = a1;
            sA[w][base + 2] = a2; sA[w][base + 3] = at;
        }
    }
    __syncwarp();

    // ---- coalesced global stores ----
    // X row: 512 bf16 = 256 b32, pattern [hi(0..159) | lo(0..159) | hi(0..159) | 0 x32]
    {
        __nv_bfloat162* xr2 = (__nv_bfloat162*)(g_Xh + (size_t)b * KC);
        for (int i = lane; i < 256; i += 32) {
            int p0 = 2 * i, p1 = p0 + 1;
            __nv_bfloat16 v0, v1;
            v0 = (p0 < 160) ? hb(sX[w][p0])
               : (p0 < 320) ? lb(sX[w][p0 - 160])
               : (p0 < 480) ? hb(sX[w][p0 - 320]) : hb(0.f);
            v1 = (p1 < 160) ? hb(sX[w][p1])
               : (p1 < 320) ? lb(sX[w][p1 - 160])
               : (p1 < 480) ? hb(sX[w][p1 - 320]) : hb(0.f);
            xr2[i] = __nv_bfloat162(v0, v1);
        }
    }
    // A row: 48 float4
    {
        float4* ar = (float4*)(g_A + (size_t)b * 192);
        const float4* sa = (const float4*)&sA[w][0];
        for (int i = lane; i < 48; i += 32) ar[i] = sa[i];
    }
    // W-translation term: out[b][k*3+c] = sum_j A[b][j][c*4+3] * W[k][j]
    // (initializes out; mma epilogue atomically adds the rotation part)
    for (int o = lane; o < 63; o += 32) {
        int k = (o * 21846) >> 16;      // o/3 for o < 63
        int c = o - k * 3;
        float acc = 0.f;
        #pragma unroll
        for (int j = 0; j < 16; j++)
            acc = fmaf(sA[w][j * 12 + c * 4 + 3], g_W[k * 16 + j], acc);
        out[(size_t)b * 63 + o] = acc;
    }
}

// =====================================================================
// Kernel 3: FUSED bf16 GEMM + joint reduction (R10-proven form).
// GEMM tile 128x128 (bm=128 batches, bn=128 cols = 2 complete joints).
// Epilogue: stage fp32 tile in smem, contract with A[b, j0..j0+1],
// atomicAdd 63 partials per batch into out.
// =====================================================================
__global__ __launch_bounds__(256) void mma_fused(float* __restrict__ out)
{
    __shared__ __align__(128) char smem[49152];

    const int tid = threadIdx.x;
    const int wid = tid >> 5, lane = tid & 31;
    const int bn0 = blockIdx.x * 128;
    const int bm0 = blockIdx.y * 128;
    const int j0  = blockIdx.x * 2;          // first joint of this N tile
    const int warp_m = (wid & 1) * 64;
    const int warp_n = (wid >> 1) * 32;

    const uint32_t smA_u = (uint32_t)__cvta_generic_to_shared(smem);
    const uint32_t smB_u = smA_u + 24576;

    float acc[4][4][4];
    #pragma unroll
    for (int mt = 0; mt < 4; mt++)
        #pragma unroll
        for (int nt = 0; nt < 4; nt++)
            #pragma unroll
            for (int q = 0; q < 4; q++) acc[mt][nt][q] = 0.f;

    auto load_chunk = [&](int kc, int st) {
        #pragma unroll
        for (int i = 0; i < 2; i++) {
            int idx = i * 256 + tid;
            int row = idx >> 2, c16 = idx & 3;
            uint32_t off = SWA((uint32_t)(row * 64 + c16 * 16));
            cp16(smA_u + st * 8192 + off,
                 g_Xh + (size_t)(bm0 + row) * KC + kc * BKC + c16 * 8);
        }
        #pragma unroll
        for (int i = 0; i < 2; i++) {
            int idx = i * 256 + tid;
            int row = idx >> 4, c16 = idx & 15;
            uint32_t off = SWB((uint32_t)(row * 256 + c16 * 16));
            cp16(smB_u + st * 8192 + off,
                 g_Cb + (size_t)(kc * BKC + row) * NP + bn0 + c16 * 8);
        }
    };

    load_chunk(0, 0); CP_COMMIT();
    load_chunk(1, 1); CP_COMMIT();

    const int r15 = lane & 15;
    const int kq  = lane >> 4;

    #pragma unroll 1
    for (int kc = 0; kc < NCH; kc++) {
        CP_WAIT1();
        __syncthreads();
        int nk = kc + 2;
        if (nk < NCH) load_chunk(nk, nk % 3);
        CP_COMMIT();

        int st = kc % 3;
        #pragma unroll
        for (int ks = 0; ks < 2; ks++) {
            uint32_t a[4][4], b[4][2];
            #pragma unroll
            for (int mt = 0; mt < 4; mt++) {
                uint32_t off = (uint32_t)((warp_m + mt * 16 + r15) * 64
                                          + (ks * 16 + kq * 8) * 2);
                ldsm_x4(a[mt], smA_u + st * 8192 + SWA(off));
            }
            #pragma unroll
            for (int nt = 0; nt < 4; nt++) {
                uint32_t off = (uint32_t)((ks * 16 + r15) * 256
                                          + (warp_n + nt * 8) * 2);
                ldsm_x2_t(b[nt], smB_u + st * 8192 + SWB(off));
            }
            #pragma unroll
            for (int mt = 0; mt < 4; mt++)
                #pragma unroll
                for (int nt = 0; nt < 4; nt++)
                    mma16816(acc[mt][nt], a[mt], b[nt]);
        }
    }

    // ================= fused epilogue =================
    CP_WAIT0();
    __syncthreads();      // pipeline buffers dead; smem arena is free

    float* sA2 = (float*)smem;                 // [128 batches][24] = 12 KB
    float* sM  = (float*)(smem + 12288);       // [64 rows][132]    = 33 KB

    // load A slice for this CTA's 128 batches, joints j0, j0+1 (6 float4/batch)
    {
        const float4* gA4 = (const float4*)(g_A + (size_t)bm0 * 192);
        float4* sA4 = (float4*)sA2;
        #pragma unroll
        for (int i = tid; i < 768; i += 256) {
            int bl = i / 6, q = i - bl * 6;
            sA4[bl * 6 + q] = gA4[bl * 48 + j0 * 3 + q];
        }
    }

    #pragma unroll
    for (int h = 0; h < 2; h++) {
        // warps owning rows [h*64, h*64+64) store their accumulators
        if ((wid & 1) == h) {
            #pragma unroll
            for (int mt = 0; mt < 4; mt++) {
                int rl = mt * 16 + (lane >> 2);
                #pragma unroll
                for (int nt = 0; nt < 4; nt++) {
                    int c = warp_n + nt * 8 + (lane & 3) * 2;
                    *(float2*)&sM[rl * 132 + c] =
                        make_float2(acc[mt][nt][0], acc[mt][nt][1]);
                    *(float2*)&sM[(rl + 8) * 132 + c] =
                        make_float2(acc[mt][nt][2], acc[mt][nt][3]);
                }
            }
        }
        __syncthreads();

        // contract: for each (batch-in-half, o<63): sum over 2 joints
        #pragma unroll
        for (int it = 0; it < 16; it++) {
            int idx = it * 256 + tid;            // 0..4095
            int bl = idx >> 6, o = idx & 63;
            if (o < 63) {
                int k = (o * 21846) >> 16;       // o/3
                int c = o - k * 3;
                int bglob = h * 64 + bl;
                const float* m = &sM[bl * 132 + k * 3];
                float4 a0 = *(const float4*)&sA2[bglob * 24 + c * 4];
                float4 a1 = *(const float4*)&sA2[bglob * 24 + 12 + c * 4];
                float acc2;
                acc2 = a0.x * m[0];
                acc2 = fmaf(a0.y, m[1], acc2);
                acc2 = fmaf(a0.z, m[2], acc2);
                acc2 = fmaf(a1.x, m[64], acc2);
                acc2 = fmaf(a1.y, m[65], acc2);
                acc2 = fmaf(a1.z, m[66], acc2);
                atomicAdd(&out[(size_t)(bm0 + bglob) * 63 + o], acc2);
            }
        }
        __syncthreads();
    }
}

// =====================================================================
extern "C" void kernel_launch(void* const* d_in, const int* in_sizes, int n_in,
                              void* d_out, int out_size)
{
    const float* beta  = (const float*)d_in[0];
    const float* theta = (const float*)d_in[1];
    const float* wrist = (const float*)d_in[2];
    const float* vt    = (const float*)d_in[3];
    const float* sd    = (const float*)d_in[4];
    const float* pd    = (const float*)d_in[5];
    const float* Jr    = (const float*)d_in[6];
    const float* hc    = (const float*)d_in[7];
    const float* hm    = (const float*)d_in[8];
    const float* wts   = (const float*)d_in[9];
    float* out = (float*)d_out;

    precomp_part<<<NFT * NVS + 72, 384>>>(vt, sd, pd, Jr, wts);
    fk_kernel<<<1216, 256>>>(beta, theta, wrist, hc, hm, out);
    mma_fused<<<dim3(NP / 128, NB / 128), 256>>>(out);
}

// round 13
// speedup vs baseline: 1.2484x; 1.0556x over previous
#include <cuda_runtime.h>
#include <cuda_bf16.h>
#include <math.h>
#include <stdint.h>

// Problem constants
#define NB   8192          // batch
#define NV   778           // vertices
#define KC   448           // packed K stride: [Xhi 0..145 | Xlo 146..291 | Xhi 292..437 | 0]
#define NP   1024          // padded N = 16 joints * 64 (63 used per joint)
#define BKC  32            // k per pipeline chunk
#define NCH  14            // 448 / 32 chunks
#define NVS  16            // vertex splits for precomp_C
#define VPB  49            // verts per split block (16*49=784>=778)
#define NFT  37            // f tiles of 4 (37*4=148>=146)

// ---------------- scratch (device globals; zero-initialized at load) ----------------
__device__ __nv_bfloat16 g_Xh[(size_t)NB * KC];   // [b][k]  A operand bf16
__device__ __nv_bfloat16 g_Cb[(size_t)KC * NP];   // [k][j*64 + k21*3 + d]  B operand bf16
__device__ float  g_Cp[NVS * 146 * 1008];         // fp32 partials of C
__device__ float  g_A[NB * 192];                  // [b][j][3x4]
__device__ float  g_Js[480];
__device__ float  g_J0[48];
__device__ float  g_W[336];

// ---------------- helpers ----------------
__device__ __forceinline__ __nv_bfloat16 hb(float x) { return __float2bfloat16(x); }
__device__ __forceinline__ __nv_bfloat16 lb(float x) {
    return __float2bfloat16(x - __bfloat162float(__float2bfloat16(x)));
}
__device__ __forceinline__ void ldsm_x4(uint32_t* r, uint32_t addr) {
    asm volatile("ldmatrix.sync.aligned.m8n8.x4.shared.b16 {%0,%1,%2,%3}, [%4];"
                 : "=r"(r[0]), "=r"(r[1]), "=r"(r[2]), "=r"(r[3]) : "r"(addr));
}
__device__ __forceinline__ void ldsm_x2_t(uint32_t* r, uint32_t addr) {
    asm volatile("ldmatrix.sync.aligned.m8n8.x2.trans.shared.b16 {%0,%1}, [%2];"
                 : "=r"(r[0]), "=r"(r[1]) : "r"(addr));
}
__device__ __forceinline__ void mma16816(float* d, const uint32_t* a, const uint32_t* b) {
    asm volatile("mma.sync.aligned.m16n8k16.row.col.f32.bf16.bf16.f32 "
                 "{%0,%1,%2,%3}, {%4,%5,%6,%7}, {%8,%9}, {%0,%1,%2,%3};"
                 : "+f"(d[0]), "+f"(d[1]), "+f"(d[2]), "+f"(d[3])
                 : "r"(a[0]), "r"(a[1]), "r"(a[2]), "r"(a[3]), "r"(b[0]), "r"(b[1]));
}
__device__ __forceinline__ void cp16(uint32_t saddr, const void* g) {
    asm volatile("cp.async.cg.shared.global [%0], [%1], 16;" :: "r"(saddr), "l"(g) : "memory");
}
#define CP_COMMIT() asm volatile("cp.async.commit_group;" ::: "memory")
#define CP_WAIT1()  asm volatile("cp.async.wait_group 1;" ::: "memory")
#define CP_WAIT0()  asm volatile("cp.async.wait_group 0;" ::: "memory")
// A staging: 64B rows (32 halfs), swizzle bits[5:4] ^= bits[7:6]
#define SWA(o) ((o) ^ (((o) >> 2) & 0x30))
// B staging: 256B rows (128 halfs), swizzle bits[6:4] ^= bits[10:8]
#define SWB(o) ((o) ^ (((o) >> 4) & 0x70))

// =====================================================================
// Kernel 1: precomp_part — blocks 0..591: C partials, f-blocked (4 f/block),
//           16 vertex splits; blocks 592..663: small reductions (Js, J0, W).
// =====================================================================
__global__ __launch_bounds__(384) void precomp_part(
    const float* __restrict__ vt, const float* __restrict__ sd,
    const float* __restrict__ pd, const float* __restrict__ Jr,
    const float* __restrict__ wts)
{
    __shared__ float sW[VPB * 16];          // [v][j]
    __shared__ float sJr[VPB * 21];         // [v][k]
    __shared__ __align__(16) float sB[VPB * 12];   // [v][f'*3+d]

    int t = threadIdx.x;
    int bid = blockIdx.x;

    if (bid < NFT * NVS) {
        int ft = bid >> 4;
        int vs = bid & 15;
        int f0 = ft * 4;
        int vstart = vs * VPB;

        // stage w, Jr (zero-padded beyond NV)
        for (int i = t; i < VPB * 16; i += 384) {
            int vv = i >> 4, j = i & 15;
            int v = vstart + vv;
            sW[i] = (v < NV) ? wts[v * 16 + j] : 0.f;
        }
        for (int i = t; i < VPB * 21; i += 384) {
            int vv = i / 21, k = i - vv * 21;
            int v = vstart + vv;
            sJr[i] = (v < NV) ? Jr[v * 21 + k] : 0.f;
        }
        // stage 4 basis rows interleaved: sB[v][fp*3+d]
        #pragma unroll
        for (int fp = 0; fp < 4; fp++) {
            int f = f0 + fp;
            const float* brow = (f == 0) ? vt : ((f <= 10) ? (sd + (f - 1) * 2334)
                                                           : (pd + (f - 11) * 2334));
            bool fvalid = (f < 146);
            for (int i = t; i < VPB * 3; i += 384) {
                int vv = i / 3, d = i - vv * 3;
                int v = vstart + vv;
                sB[vv * 12 + fp * 3 + d] =
                    (fvalid && v < NV) ? brow[v * 3 + d] : 0.f;
            }
        }
        __syncthreads();

        if (t < 336) {
            int j = t / 21, k = t - j * 21;
            float acc[12];
            #pragma unroll
            for (int i = 0; i < 12; i++) acc[i] = 0.f;

            #pragma unroll 2
            for (int vv = 0; vv < VPB; vv++) {
                float p = sW[vv * 16 + j] * sJr[vv * 21 + k];
                float4 b0 = *(const float4*)&sB[vv * 12 + 0];
                float4 b1 = *(const float4*)&sB[vv * 12 + 4];
                float4 b2 = *(const float4*)&sB[vv * 12 + 8];
                acc[0]  = fmaf(p, b0.x, acc[0]);
                acc[1]  = fmaf(p, b0.y, acc[1]);
                acc[2]  = fmaf(p, b0.z, acc[2]);
                acc[3]  = fmaf(p, b0.w, acc[3]);
                acc[4]  = fmaf(p, b1.x, acc[4]);
                acc[5]  = fmaf(p, b1.y, acc[5]);
                acc[6]  = fmaf(p, b1.z, acc[6]);
                acc[7]  = fmaf(p, b1.w, acc[7]);
                acc[8]  = fmaf(p, b2.x, acc[8]);
                acc[9]  = fmaf(p, b2.y, acc[9]);
                acc[10] = fmaf(p, b2.z, acc[10]);
                acc[11] = fmaf(p, b2.w, acc[11]);
            }
            #pragma unroll
            for (int fp = 0; fp < 4; fp++) {
                int f = f0 + fp;
                if (f < 146) {
                    float* dst = g_Cp + ((size_t)vs * 146 + f) * 1008 + t * 3;
                    dst[0] = acc[fp * 3 + 0];
                    dst[1] = acc[fp * 3 + 1];
                    dst[2] = acc[fp * 3 + 2];
                }
            }
        }
    } else {
        int gw   = (bid - NFT * NVS) * 12 + (t >> 5);    // 0..863
        int lane = t & 31;
        float acc = 0.f;
        if (gw < 480) {                 // Js[s][j][c]
            int s = gw / 48, r = gw % 48, j = r / 3, c = r % 3;
            for (int v = lane; v < NV; v += 32)
                acc = fmaf(Jr[v * 21 + j], sd[s * 2334 + v * 3 + c], acc);
        } else if (gw < 528) {          // J0[j][c]
            int idx = gw - 480, j = idx / 3, c = idx % 3;
            for (int v = lane; v < NV; v += 32)
                acc = fmaf(Jr[v * 21 + j], vt[v * 3 + c], acc);
        } else {                        // W[k][j]
            int idx = gw - 528, k = idx / 16, j = idx % 16;
            for (int v = lane; v < NV; v += 32)
                acc = fmaf(Jr[v * 21 + k], wts[v * 16 + j], acc);
        }
        #pragma unroll
        for (int off = 16; off > 0; off >>= 1)
            acc += __shfl_down_sync(0xffffffffu, acc, off);
        if (lane == 0) {
            if (gw < 480)      g_Js[gw] = acc;
            else if (gw < 528) g_J0[gw - 480] = acc;
            else               g_W[gw - 528] = acc;
        }
    }
}

// =====================================================================
// Kernel 2: fk_kernel — blocks 0..1023: per-batch FK (g_Xh, g_A) AND the
//           W-translation term written to out[b][*] (initializes out);
//           blocks 1024..1215: combine C partials -> bf16, packed-K layout.
// =====================================================================
__global__ __launch_bounds__(256) void fk_kernel(
    const float* __restrict__ beta, const float* __restrict__ theta,
    const float* __restrict__ wrist, const float* __restrict__ hc,
    const float* __restrict__ hm, float* __restrict__ out)
{
    if (blockIdx.x >= 1024) {
        // ---- combine C partials, write rows f / 146+f / 292+f ----
        int idx = (blockIdx.x - 1024) * 256 + threadIdx.x;   // (f, o336)
        if (idx >= 146 * 336) return;
        int f = idx / 336, o = idx % 336;
        int j = o / 21, k21 = o % 21;
        int col = j * 64 + k21 * 3;
        #pragma unroll
        for (int c = 0; c < 3; c++) {
            int o3 = o * 3 + c;
            float v = 0.f;
            #pragma unroll
            for (int vs = 0; vs < NVS; vs++)
                v += g_Cp[((size_t)vs * 146 + f) * 1008 + o3];
            g_Cb[(size_t)f * NP + col + c]         = hb(v);
            g_Cb[(size_t)(146 + f) * NP + col + c] = hb(v);
            g_Cb[(size_t)(292 + f) * NP + col + c] = lb(v);
        }
        return;
    }

    __shared__ float sE[8][48];
    __shared__ float sR[8][16][9];
    __shared__ float sJ[8][16][3];
    __shared__ float sG[8][16][12];
    __shared__ float sX[8][160];
    __shared__ float sA[8][192];

    int w = threadIdx.x >> 5, lane = threadIdx.x & 31;
    int b = blockIdx.x * 8 + w;

    // zero X row (incl. pads)
    for (int e = lane; e < 160; e += 32) sX[w][e] = 0.f;

    for (int e = lane; e < 45; e += 32) {
        float v = hm[e];
        #pragma unroll
        for (int s = 0; s < 10; s++)
            v = fmaf(theta[b * 10 + s], hc[s * 45 + e], v);
        sE[w][e] = v;
    }
    __syncwarp();

    if (lane < 16) {
        float r0, r1, r2;
        if (lane == 0) { r0 = wrist[b * 3]; r1 = wrist[b * 3 + 1]; r2 = wrist[b * 3 + 2]; }
        else { int e = (lane - 1) * 3; r0 = sE[w][e]; r1 = sE[w][e + 1]; r2 = sE[w][e + 2]; }
        float t0 = r0 + 1e-8f, t1 = r1 + 1e-8f, t2 = r2 + 1e-8f;
        float ang = sqrtf(t0 * t0 + t1 * t1 + t2 * t2);
        float inv = 1.0f / ang;
        float x = r0 * inv, y = r1 * inv, z = r2 * inv;
        float s, c;
        sincosf(ang, &s, &c);
        float ic = 1.0f - c;
        float R[9];
        R[0] = 1.0f - ic * (y * y + z * z);
        R[1] = -s * z + ic * x * y;
        R[2] =  s * y + ic * x * z;
        R[3] =  s * z + ic * x * y;
        R[4] = 1.0f - ic * (x * x + z * z);
        R[5] = -s * x + ic * y * z;
        R[6] = -s * y + ic * x * z;
        R[7] =  s * x + ic * y * z;
        R[8] = 1.0f - ic * (x * x + y * y);
        #pragma unroll
        for (int m = 0; m < 9; m++) sR[w][lane][m] = R[m];
        if (lane >= 1) {
            int s0 = 11 + (lane - 1) * 9;
            #pragma unroll
            for (int m = 0; m < 9; m++)
                sX[w][s0 + m] = R[m] - ((m == 0 || m == 4 || m == 8) ? 1.0f : 0.0f);
        }
    }
    if (lane == 0)  sX[w][0] = 1.0f;
    if (lane < 10)  sX[w][1 + lane] = beta[b * 10 + lane];

    if (lane < 16) {
        float jx = g_J0[lane * 3 + 0], jy = g_J0[lane * 3 + 1], jz = g_J0[lane * 3 + 2];
        #pragma unroll
        for (int s = 0; s < 10; s++) {
            float bs = beta[b * 10 + s];
            jx = fmaf(bs, g_Js[s * 48 + lane * 3 + 0], jx);
            jy = fmaf(bs, g_Js[s * 48 + lane * 3 + 1], jy);
            jz = fmaf(bs, g_Js[s * 48 + lane * 3 + 2], jz);
        }
        sJ[w][lane][0] = jx; sJ[w][lane][1] = jy; sJ[w][lane][2] = jz;
    }
    __syncwarp();

    if (lane == 0) {
        #pragma unroll
        for (int c = 0; c < 3; c++) {
            #pragma unroll
            for (int d = 0; d < 3; d++) sG[w][0][c * 4 + d] = sR[w][0][c * 3 + d];
            sG[w][0][c * 4 + 3] = sJ[w][0][c];
        }
    }
    __syncwarp();

    if (lane < 5) {
        float pr[9], pt[3];
        #pragma unroll
        for (int c = 0; c < 3; c++) {
            #pragma unroll
            for (int d = 0; d < 3; d++) pr[c * 3 + d] = sG[w][0][c * 4 + d];
            pt[c] = sG[w][0][c * 4 + 3];
        }
        int p = 0;
        #pragma unroll
        for (int st = 0; st < 3; st++) {
            int j = 1 + lane * 3 + st;
            float rj[9];
            #pragma unroll
            for (int m = 0; m < 9; m++) rj[m] = sR[w][j][m];
            float nr[9], nt[3];
            #pragma unroll
            for (int c = 0; c < 3; c++)
                #pragma unroll
                for (int d = 0; d < 3; d++)
                    nr[c * 3 + d] = pr[c * 3 + 0] * rj[0 * 3 + d]
                                  + pr[c * 3 + 1] * rj[1 * 3 + d]
                                  + pr[c * 3 + 2] * rj[2 * 3 + d];
            float dx = sJ[w][j][0] - sJ[w][p][0];
            float dy = sJ[w][j][1] - sJ[w][p][1];
            float dz = sJ[w][j][2] - sJ[w][p][2];
            #pragma unroll
            for (int c = 0; c < 3; c++)
                nt[c] = pr[c * 3 + 0] * dx + pr[c * 3 + 1] * dy + pr[c * 3 + 2] * dz + pt[c];
            #pragma unroll
            for (int c = 0; c < 3; c++) {
                #pragma unroll
                for (int d = 0; d < 3; d++) sG[w][j][c * 4 + d] = nr[c * 3 + d];
                sG[w][j][c * 4 + 3] = nt[c];
            }
            #pragma unroll
            for (int m = 0; m < 9; m++) pr[m] = nr[m];
            pt[0] = nt[0]; pt[1] = nt[1]; pt[2] = nt[2];
            p = j;
        }
    }
    __syncwarp();

    if (lane < 16) {
        float jx = sJ[w][lane][0], jy = sJ[w][lane][1], jz = sJ[w][lane][2];
        #pragma unroll
        for (int c = 0; c < 3; c++) {
            float a0 = sG[w][lane][c * 4 + 0];
            float a1 = sG[w][lane][c * 4 + 1];
            float a2 = sG[w][lane][c * 4 + 2];
            float at = sG[w][lane][c * 4 + 3] - (a0 * jx + a1 * jy + a2 * jz);
            int base = lane * 12 + c * 4;
            sA[w][base + 0] = a0; sA[w][base + 1] = a1;
            sA[w][base + 2] = a2; sA[w][base + 3] = at;
        }
    }
    __syncwarp();

    // ---- coalesced global stores ----
    // X row: 448 bf16 = 224 b32, pattern [hi(0..145) | lo(0..145) | hi(0..145) | 0]
    {
        __nv_bfloat162* xr2 = (__nv_bfloat162*)(g_Xh + (size_t)b * KC);
        for (int i = lane; i < 224; i += 32) {
            int p0 = 2 * i, p1 = p0 + 1;
            __nv_bfloat16 v0, v1;
            v0 = (p0 < 146) ? hb(sX[w][p0])
               : (p0 < 292) ? lb(sX[w][p0 - 146])
               : (p0 < 438) ? hb(sX[w][p0 - 292]) : hb(0.f);
            v1 = (p1 < 146) ? hb(sX[w][p1])
               : (p1 < 292) ? lb(sX[w][p1 - 146])
               : (p1 < 438) ? hb(sX[w][p1 - 292]) : hb(0.f);
            xr2[i] = __nv_bfloat162(v0, v1);
        }
    }
    // A row: 48 float4
    {
        float4* ar = (float4*)(g_A + (size_t)b * 192);
        const float4* sa = (const float4*)&sA[w][0];
        for (int i = lane; i < 48; i += 32) ar[i] = sa[i];
    }
    // W-translation term: out[b][k*3+c] = sum_j A[b][j][c*4+3] * W[k][j]
    // (initializes out; mma epilogue atomically adds the rotation part)
    for (int o = lane; o < 63; o += 32) {
        int k = (o * 21846) >> 16;      // o/3 for o < 63
        int c = o - k * 3;
        float acc = 0.f;
        #pragma unroll
        for (int j = 0; j < 16; j++)
            acc = fmaf(sA[w][j * 12 + c * 4 + 3], g_W[k * 16 + j], acc);
        out[(size_t)b * 63 + o] = acc;
    }
}

// =====================================================================
// Kernel 3: FUSED bf16 GEMM + joint reduction.
// GEMM tile 128x128 (bm=128 batches, bn=128 cols = 2 complete joints).
// Epilogue: stage fp32 tile in smem, contract with A[b, j0..j0+1],
// atomicAdd 63 partials per batch into out.
// =====================================================================
__global__ __launch_bounds__(256) void mma_fused(float* __restrict__ out)
{
    __shared__ __align__(128) char smem[49152];

    const int tid = threadIdx.x;
    const int wid = tid >> 5, lane = tid & 31;
    const int bn0 = blockIdx.x * 128;
    const int bm0 = blockIdx.y * 128;
    const int j0  = blockIdx.x * 2;          // first joint of this N tile
    const int warp_m = (wid & 1) * 64;
    const int warp_n = (wid >> 1) * 32;

    const uint32_t smA_u = (uint32_t)__cvta_generic_to_shared(smem);
    const uint32_t smB_u = smA_u + 24576;

    float acc[4][4][4];
    #pragma unroll
    for (int mt = 0; mt < 4; mt++)
        #pragma unroll
        for (int nt = 0; nt < 4; nt++)
            #pragma unroll
            for (int q = 0; q < 4; q++) acc[mt][nt][q] = 0.f;

    auto load_chunk = [&](int kc, int st) {
        #pragma unroll
        for (int i = 0; i < 2; i++) {
            int idx = i * 256 + tid;
            int row = idx >> 2, c16 = idx & 3;
            uint32_t off = SWA((uint32_t)(row * 64 + c16 * 16));
            cp16(smA_u + st * 8192 + off,
                 g_Xh + (size_t)(bm0 + row) * KC + kc * BKC + c16 * 8);
        }
        #pragma unroll
        for (int i = 0; i < 2; i++) {
            int idx = i * 256 + tid;
            int row = idx >> 4, c16 = idx & 15;
            uint32_t off = SWB((uint32_t)(row * 256 + c16 * 16));
            cp16(smB_u + st * 8192 + off,
                 g_Cb + (size_t)(kc * BKC + row) * NP + bn0 + c16 * 8);
        }
    };

    load_chunk(0, 0); CP_COMMIT();
    load_chunk(1, 1); CP_COMMIT();

    const int r15 = lane & 15;
    const int kq  = lane >> 4;

    #pragma unroll 1
    for (int kc = 0; kc < NCH; kc++) {
        CP_WAIT1();
        __syncthreads();
        int nk = kc + 2;
        if (nk < NCH) load_chunk(nk, nk % 3);
        CP_COMMIT();

        int st = kc % 3;
        #pragma unroll
        for (int ks = 0; ks < 2; ks++) {
            uint32_t a[4][4], b[4][2];
            #pragma unroll
            for (int mt = 0; mt < 4; mt++) {
                uint32_t off = (uint32_t)((warp_m + mt * 16 + r15) * 64
                                          + (ks * 16 + kq * 8) * 2);
                ldsm_x4(a[mt], smA_u + st * 8192 + SWA(off));
            }
            #pragma unroll
            for (int nt = 0; nt < 4; nt++) {
                uint32_t off = (uint32_t)((ks * 16 + r15) * 256
                                          + (warp_n + nt * 8) * 2);
                ldsm_x2_t(b[nt], smB_u + st * 8192 + SWB(off));
            }
            #pragma unroll
            for (int mt = 0; mt < 4; mt++)
                #pragma unroll
                for (int nt = 0; nt < 4; nt++)
                    mma16816(acc[mt][nt], a[mt], b[nt]);
        }
    }

    // ================= fused epilogue =================
    CP_WAIT0();
    __syncthreads();      // pipeline buffers dead; smem arena is free

    float* sA2 = (float*)smem;                 // [128 batches][24] = 12 KB
    float* sM  = (float*)(smem + 12288);       // [64 rows][132]    = 33 KB

    // load A slice for this CTA's 128 batches, joints j0, j0+1 (6 float4/batch)
    {
        const float4* gA4 = (const float4*)(g_A + (size_t)bm0 * 192);
        float4* sA4 = (float4*)sA2;
        #pragma unroll
        for (int i = tid; i < 768; i += 256) {
            int bl = i / 6, q = i - bl * 6;
            sA4[bl * 6 + q] = gA4[bl * 48 + j0 * 3 + q];
        }
    }

    #pragma unroll
    for (int h = 0; h < 2; h++) {
        // warps owning rows [h*64, h*64+64) store their accumulators
        if ((wid & 1) == h) {
            #pragma unroll
            for (int mt = 0; mt < 4; mt++) {
                int rl = mt * 16 + (lane >> 2);
                #pragma unroll
                for (int nt = 0; nt < 4; nt++) {
                    int c = warp_n + nt * 8 + (lane & 3) * 2;
                    *(float2*)&sM[rl * 132 + c] =
                        make_float2(acc[mt][nt][0], acc[mt][nt][1]);
                    *(float2*)&sM[(rl + 8) * 132 + c] =
                        make_float2(acc[mt][nt][2], acc[mt][nt][3]);
                }
            }
        }
        __syncthreads();

        // contract: for each (batch-in-half, o<63): sum over 2 joints
        #pragma unroll
        for (int it = 0; it < 16; it++) {
            int idx = it * 256 + tid;            // 0..4095
            int bl = idx >> 6, o = idx & 63;
            if (o < 63) {
                int k = (o * 21846) >> 16;       // o/3
                int c = o - k * 3;
                int bglob = h * 64 + bl;
                const float* m = &sM[bl * 132 + k * 3];
                float4 a0 = *(const float4*)&sA2[bglob * 24 + c * 4];
                float4 a1 = *(const float4*)&sA2[bglob * 24 + 12 + c * 4];
                float acc2;
                acc2 = a0.x * m[0];
                acc2 = fmaf(a0.y, m[1], acc2);
                acc2 = fmaf(a0.z, m[2], acc2);
                acc2 = fmaf(a1.x, m[64], acc2);
                acc2 = fmaf(a1.y, m[65], acc2);
                acc2 = fmaf(a1.z, m[66], acc2);
                atomicAdd(&out[(size_t)(bm0 + bglob) * 63 + o], acc2);
            }
        }
        __syncthreads();
    }
}

// =====================================================================
extern "C" void kernel_launch(void* const* d_in, const int* in_sizes, int n_in,
                              void* d_out, int out_size)
{
    const float* beta  = (const float*)d_in[0];
    const float* theta = (const float*)d_in[1];
    const float* wrist = (const float*)d_in[2];
    const float* vt    = (const float*)d_in[3];
    const float* sd    = (const float*)d_in[4];
    const float* pd    = (const float*)d_in[5];
    const float* Jr    = (const float*)d_in[6];
    const float* hc    = (const float*)d_in[7];
    const float* hm    = (const float*)d_in[8];
    const float* wts   = (const float*)d_in[9];
    float* out = (float*)d_out;

    precomp_part<<<NFT * NVS + 72, 384>>>(vt, sd, pd, Jr, wts);
    fk_kernel<<<1216, 256>>>(beta, theta, wrist, hc, hm, out);
    mma_fused<<<dim3(NP / 128, NB / 128), 256>>>(out);
}